// round 11
// baseline (speedup 1.0000x reference)
#include <cuda_runtime.h>
#include <float.h>

// Problem constants
#define B      2
#define C      3
#define T      8
#define H      448
#define W      448
#define NKEY   4
#define L      196      // 14*14
#define GH     14
#define R      121      // 11*11
#define NS     500
#define BK     (B*NKEY) // 8
#define OUTHW  128      // s*A

#define ARG_BLOCKS_PER_KEY 63
#define N_ARG   (ARG_BLOCKS_PER_KEY * BK)     // 504 argmax blocks
#define N_GATH  ((B*C*T*OUTHW) / 16)          // 384 gather blocks (16 rows each)
#define N_TOTAL (N_ARG + N_GATH)              // 888 blocks

// Device scratch (no allocation allowed). All counters are 0 at module load
// and reset to 0 by the last gather passer each launch => every launch
// (correctness call + each replay) starts from identical state.
__device__ float g_scn[BK][R];   // normalized region scores
__device__ int   g_cnt[BK][R];   // top-1 histogram (zeroed by producer blocks)
__device__ int   g_flag[BK];     // per-key scorenorm-ready flags
__device__ int   g_done;         // argmax-blocks-finished counter (0..504)
__device__ int   g_gpass;        // gather-blocks-passed-wait counter (0..384)

// ---------------------------------------------------------------------------
// Single fused kernel, 888 blocks x 256 threads, one wave guaranteed:
//   __launch_bounds__(256,8) -> <=32 regs -> 8 blocks/SM -> 1184 slots >= 888.
//   Argmax blocks have the lowest blockIdx -> scheduled first -> even under
//   partial residency the producers always make progress (deadlock-free).
//
// Phase A (blocks 0..503): score-norm handshake (R10-proven) + per-warp
//   perturbed top-1 argmax + atomic histogram; block arrives on g_done.
// Phase B (blocks 504..887): spin on g_done==504, ballot-compact the
//   histogram, then float4 gather with 2 rows/warp (2x MLP).
// ---------------------------------------------------------------------------
__global__ __launch_bounds__(256, 8)
void fused_kernel(const float* __restrict__ x,
                  const float* __restrict__ score,
                  const float* __restrict__ noise,
                  const float* __restrict__ sigma_p,
                  const int*   __restrict__ group_id,
                  float*       __restrict__ out)
{
    const int bid  = blockIdx.x;
    const int tid  = threadIdx.x;
    const int lane = tid & 31;
    const int wrp  = tid >> 5;

    __shared__ float sc[R];          // argmax: normalized scores
    __shared__ float wmin[4], wmax[4];
    __shared__ float lo_s, inv_s;
    __shared__ float wc[R];          // gather: compacted weights
    __shared__ int   off[R];         // gather: compacted offsets
    __shared__ int   wbase[4];
    __shared__ int   nnz_s;

    if (bid < N_ARG) {
        // =================== Phase A: argmax blocks ===================
        const int bk = bid / ARG_BLOCKS_PER_KEY;
        const int xi = bid % ARG_BLOCKS_PER_KEY;

        if (xi == 0) {
            // ---- producer: normalized scores once per key ----
            float v = 0.f;
            if (tid < R) {
                const int ri = tid / 11;
                const int rj = tid % 11;
                const float* sp = score + bk * L;
                #pragma unroll
                for (int ki = 0; ki < 4; ki++)
                    #pragma unroll
                    for (int kj = 0; kj < 4; kj++)
                        v += sp[(ri + ki) * GH + (rj + kj)];
                v *= (1.f / 16.f);
            }
            if (wrp < 4) {
                float mn = (tid < R) ? v : FLT_MAX;
                float mx = (tid < R) ? v : -FLT_MAX;
                #pragma unroll
                for (int o = 16; o > 0; o >>= 1) {
                    mn = fminf(mn, __shfl_down_sync(0xffffffffu, mn, o));
                    mx = fmaxf(mx, __shfl_down_sync(0xffffffffu, mx, o));
                }
                if (lane == 0) { wmin[wrp] = mn; wmax[wrp] = mx; }
            }
            __syncthreads();
            if (tid == 0) {
                float lo = fminf(fminf(wmin[0], wmin[1]), fminf(wmin[2], wmin[3]));
                float hi = fmaxf(fmaxf(wmax[0], wmax[1]), fmaxf(wmax[2], wmax[3]));
                lo_s  = lo;
                inv_s = 1.f / (hi - lo + 1e-5f);
            }
            __syncthreads();
            if (tid < R) {
                float nv = (v - lo_s) * inv_s;
                sc[tid] = nv;
                g_scn[bk][tid] = nv;
                g_cnt[bk][tid] = 0;
            }
            __syncthreads();
            if (tid == 0) {
                __threadfence();
                atomicExch(&g_flag[bk], 1);
            }
        } else {
            // ---- consumer: wait for this key's producer ----
            if (tid == 0) {
                while (atomicAdd(&g_flag[bk], 0) == 0) __nanosleep(32);
            }
            __syncthreads();
            if (tid < R) sc[tid] = __ldcg(&g_scn[bk][tid]);
            __syncthreads();
        }

        // ---- one warp per sample ----
        const int n = xi * 8 + wrp;
        if (n < NS) {
            const float sigma = sigma_p[0];
            const float* nn = noise + ((size_t)bk * NS + n) * R;

            // warp argmax, first-max / lowest-index tie-break (lax.top_k)
            float best = -FLT_MAX;
            int   bi   = 0;
            #pragma unroll
            for (int j = 0; j < 4; j++) {
                int r = lane + 32 * j;
                if (r < R) {
                    float p = fmaf(nn[r], sigma, sc[r]);
                    if (p > best) { best = p; bi = r; }
                }
            }
            #pragma unroll
            for (int o = 16; o > 0; o >>= 1) {
                float v2 = __shfl_down_sync(0xffffffffu, best, o);
                int   i2 = __shfl_down_sync(0xffffffffu, bi,   o);
                if (v2 > best || (v2 == best && i2 < bi)) { best = v2; bi = i2; }
            }
            if (lane == 0) atomicAdd(&g_cnt[bk][bi], 1);   // order-independent
        }
        __syncthreads();
        if (tid == 0) {
            __threadfence();                 // release histogram updates
            atomicAdd(&g_done, 1);           // this block's arrival
        }
    } else {
        // =================== Phase B: gather blocks ===================
        // wait for all 504 argmax blocks
        if (tid == 0) {
            while (atomicAdd(&g_done, 0) < N_ARG) __nanosleep(64);
        }
        __syncthreads();

        const int gb      = bid - N_ARG;          // 0..383
        const int rowbase = gb * 16;               // 16 rows share (b,c,t)
        const int rowhi   = rowbase >> 7;          // (b*3+c)*8 + t
        const int y0      = rowbase & (OUTHW - 1);
        const int t       = rowhi & 7;
        const int bc      = rowhi >> 3;
        const int b       = bc / 3;

        const int bk = b * NKEY + group_id[b * T + t];

        // ballot compaction of this key's histogram (order-preserving)
        int  cnt = (tid < R) ? __ldcg(&g_cnt[bk][tid]) : 0;
        bool p   = (cnt > 0);
        unsigned m = __ballot_sync(0xffffffffu, p);
        int within = __popc(m & ((1u << lane) - 1u));
        if (wrp < 4 && lane == 0) wbase[wrp] = __popc(m);
        __syncthreads();
        if (tid == 0) {
            int s = 0;
            #pragma unroll
            for (int w2 = 0; w2 < 4; w2++) { int tt = wbase[w2]; wbase[w2] = s; s += tt; }
            nnz_s = s;
        }
        __syncthreads();
        if (p) {
            int pos = wbase[wrp] + within;
            wc[pos]  = (float)cnt * (1.f / (float)NS);
            off[pos] = (tid / 11) * 32 * W + (tid % 11) * 32;
        }
        __syncthreads();

        // release bookkeeping: the LAST gather block to pass resets state.
        // At that point every consumer of g_done/g_flag/g_gpass has passed.
        if (tid == 0) {
            int old = atomicAdd(&g_gpass, 1);
            if (old == N_GATH - 1) {
                g_done  = 0;
                g_gpass = 0;
                #pragma unroll
                for (int k = 0; k < BK; k++) g_flag[k] = 0;
                __threadfence();
            }
        }

        // gather: 2 rows per warp (rows y0+wrp and y0+wrp+8), float4 lanes
        const int nnz = nnz_s;
        const int y1 = y0 + wrp;
        const int y2 = y1 + 8;
        const size_t plane = ((size_t)bc * T + t) * H;
        const size_t xb1 = (plane + y1) * W + lane * 4;
        const size_t xb2 = (plane + y2) * W + lane * 4;

        float4 a1 = make_float4(0.f, 0.f, 0.f, 0.f);
        float4 a2 = make_float4(0.f, 0.f, 0.f, 0.f);
        #pragma unroll 2
        for (int i = 0; i < nnz; i++) {
            const float w = wc[i];
            const int   o = off[i];
            const float4 v1 = *reinterpret_cast<const float4*>(x + xb1 + o);
            const float4 v2 = *reinterpret_cast<const float4*>(x + xb2 + o);
            a1.x = fmaf(w, v1.x, a1.x); a1.y = fmaf(w, v1.y, a1.y);
            a1.z = fmaf(w, v1.z, a1.z); a1.w = fmaf(w, v1.w, a1.w);
            a2.x = fmaf(w, v2.x, a2.x); a2.y = fmaf(w, v2.y, a2.y);
            a2.z = fmaf(w, v2.z, a2.z); a2.w = fmaf(w, v2.w, a2.w);
        }

        *reinterpret_cast<float4*>(out + ((size_t)(rowbase + wrp))     * OUTHW + lane * 4) = a1;
        *reinterpret_cast<float4*>(out + ((size_t)(rowbase + wrp + 8)) * OUTHW + lane * 4) = a2;
    }
}

// ---------------------------------------------------------------------------
// Launch: inputs (metadata order): x, score, noise, sigma, group_id
// ONE graph node.
// ---------------------------------------------------------------------------
extern "C" void kernel_launch(void* const* d_in, const int* in_sizes, int n_in,
                              void* d_out, int out_size)
{
    const float* x        = (const float*)d_in[0];
    const float* score    = (const float*)d_in[1];
    const float* noise    = (const float*)d_in[2];
    const float* sigma    = (const float*)d_in[3];
    const int*   group_id = (const int*)  d_in[4];
    float*       out      = (float*)d_out;

    fused_kernel<<<N_TOTAL, 256>>>(x, score, noise, sigma, group_id, out);
}